// round 2
// baseline (speedup 1.0000x reference)
#include <cuda_runtime.h>
#include <cstdint>

// out[n, d] = x[n, d] * w[d];  N = DIM = 8192, fp32.
// Column-owning layout: each thread handles one fixed float4-column and
// streams down rows. Weight loaded ONCE into registers; loop body is a pure
// LDG.128 -> 4xFMUL -> STG.128 stream with 4 independent loads in flight.

static constexpr int DIM   = 8192;
static constexpr int DIM4  = DIM / 4;        // 2048 float4 columns
static constexpr int THREADS = 256;
static constexpr int COLBLOCKS = DIM4 / THREADS;   // 8 column-blocks cover a row
static constexpr int ROWGROUPS = 256;              // row phases
static constexpr int UNROLL = 4;

__global__ void __launch_bounds__(THREADS)
diag_scale_col_kernel(const float4* __restrict__ x,
                      const float4* __restrict__ w4,
                      float4* __restrict__ out,
                      int n_rows)
{
    const int cb = blockIdx.x & (COLBLOCKS - 1);       // column block 0..7
    const int rg = blockIdx.x >> 3;                    // row group 0..ROWGROUPS-1
    const int col4 = cb * THREADS + threadIdx.x;       // fixed column for this thread

    const float4 wv = __ldg(&w4[col4]);                // loaded once, lives in regs

    const long long rstride = (long long)ROWGROUPS * DIM4;     // elems between handled rows
    long long idx = (long long)rg * DIM4 + col4;

    const int rows_per_thread = n_rows / ROWGROUPS;    // 32 for N=8192

    for (int it = 0; it < rows_per_thread / UNROLL; ++it) {
        float4 v[UNROLL];
        #pragma unroll
        for (int u = 0; u < UNROLL; ++u)
            v[u] = x[idx + (long long)u * rstride];    // 4 independent LDG.128 in flight
        #pragma unroll
        for (int u = 0; u < UNROLL; ++u) {
            v[u].x *= wv.x;
            v[u].y *= wv.y;
            v[u].z *= wv.z;
            v[u].w *= wv.w;
            out[idx + (long long)u * rstride] = v[u];
        }
        idx += (long long)UNROLL * rstride;
    }
}

// Fallback for unexpected shapes (kept from R1).
__global__ void __launch_bounds__(256)
diag_scale_fallback(const float4* __restrict__ x,
                    const float4* __restrict__ w4,
                    float4* __restrict__ out,
                    long long n4)
{
    long long i = (long long)blockIdx.x * blockDim.x + threadIdx.x;
    long long stride = (long long)gridDim.x * blockDim.x;
    for (; i < n4; i += stride) {
        float4 v = x[i];
        int col4 = (int)(i & (long long)(DIM4 - 1));
        float4 wv = __ldg(&w4[col4]);
        v.x *= wv.x; v.y *= wv.y; v.z *= wv.z; v.w *= wv.w;
        out[i] = v;
    }
}

extern "C" void kernel_launch(void* const* d_in, const int* in_sizes, int n_in,
                              void* d_out, int out_size)
{
    const float4* x  = (const float4*)d_in[0];
    const float4* w4 = (const float4*)d_in[1];
    float4* out = (float4*)d_out;

    long long n_elems = (long long)out_size;
    int dim = in_sizes[1];                 // 8192
    long long n_rows_ll = n_elems / dim;
    int n_rows = (int)n_rows_ll;

    bool fast_ok = (dim == DIM) &&
                   (n_rows % (ROWGROUPS * UNROLL) == 0);

    if (fast_ok) {
        int blocks = COLBLOCKS * ROWGROUPS;   // 8 * 256 = 2048 blocks
        diag_scale_col_kernel<<<blocks, THREADS>>>(x, w4, out, n_rows);
    } else {
        long long n4 = n_elems / 4;
        const int threads = 256;
        int blocks = 148 * 8 * 4;
        long long needed = (n4 + threads - 1) / threads;
        if ((long long)blocks > needed) blocks = (int)needed;
        diag_scale_fallback<<<blocks, threads>>>(x, w4, out, n4);
    }
}

// round 3
// speedup vs baseline: 1.0267x; 1.0267x over previous
#include <cuda_runtime.h>
#include <cstdint>

// out[n, d] = x[n, d] * w[d];  N = DIM = 8192, fp32.
// Column-owning streaming kernel:
//  - each thread owns one float4-column, weight lives in registers
//  - UNROLL=8: 8 front-batched LDG.128 (long read bursts), then 8 STG.128
//  - __ldcs / __stcs: evict-first L2 policy both directions (zero reuse data)

static constexpr int DIM   = 8192;
static constexpr int DIM4  = DIM / 4;              // 2048 float4 columns
static constexpr int THREADS = 256;
static constexpr int COLBLOCKS = DIM4 / THREADS;   // 8 column-blocks per row
static constexpr int ROWGROUPS = 256;
static constexpr int UNROLL = 8;

__global__ void __launch_bounds__(THREADS)
diag_scale_stream_kernel(const float4* __restrict__ x,
                         const float4* __restrict__ w4,
                         float4* __restrict__ out,
                         int n_rows)
{
    const int cb = blockIdx.x & (COLBLOCKS - 1);
    const int rg = blockIdx.x >> 3;
    const int col4 = cb * THREADS + threadIdx.x;

    const float4 wv = __ldg(&w4[col4]);            // once; L1-resident vector

    const long long rstride = (long long)ROWGROUPS * DIM4;
    long long idx = (long long)rg * DIM4 + col4;

    const int iters = n_rows / (ROWGROUPS * UNROLL);   // 4 for N=8192

    for (int it = 0; it < iters; ++it) {
        float4 v[UNROLL];
        #pragma unroll
        for (int u = 0; u < UNROLL; ++u)
            v[u] = __ldcs(&x[idx + (long long)u * rstride]);   // evict-first reads
        #pragma unroll
        for (int u = 0; u < UNROLL; ++u) {
            v[u].x *= wv.x;
            v[u].y *= wv.y;
            v[u].z *= wv.z;
            v[u].w *= wv.w;
            __stcs(&out[idx + (long long)u * rstride], v[u]);  // evict-first writes
        }
        idx += (long long)UNROLL * rstride;
    }
}

// Generic fallback (correct for any shape).
__global__ void __launch_bounds__(256)
diag_scale_fallback(const float4* __restrict__ x,
                    const float4* __restrict__ w4,
                    float4* __restrict__ out,
                    long long n4, int dim4)
{
    long long i = (long long)blockIdx.x * blockDim.x + threadIdx.x;
    long long stride = (long long)gridDim.x * blockDim.x;
    for (; i < n4; i += stride) {
        float4 v = __ldcs(&x[i]);
        int col4 = (int)(i % dim4);
        float4 wv = __ldg(&w4[col4]);
        v.x *= wv.x; v.y *= wv.y; v.z *= wv.z; v.w *= wv.w;
        __stcs(&out[i], v);
    }
}

extern "C" void kernel_launch(void* const* d_in, const int* in_sizes, int n_in,
                              void* d_out, int out_size)
{
    const float4* x  = (const float4*)d_in[0];
    const float4* w4 = (const float4*)d_in[1];
    float4* out = (float4*)d_out;

    long long n_elems = (long long)out_size;
    int dim = in_sizes[1];
    int n_rows = (int)(n_elems / dim);

    bool fast_ok = (dim == DIM) && (n_rows % (ROWGROUPS * UNROLL) == 0);

    if (fast_ok) {
        int blocks = COLBLOCKS * ROWGROUPS;    // 2048 blocks
        diag_scale_stream_kernel<<<blocks, THREADS>>>(x, w4, out, n_rows);
    } else {
        long long n4 = n_elems / 4;
        const int threads = 256;
        int blocks = 148 * 8 * 4;
        long long needed = (n4 + threads - 1) / threads;
        if ((long long)blocks > needed) blocks = (int)needed;
        diag_scale_fallback<<<blocks, threads>>>(x, w4, out, n4, dim / 4);
    }
}